// round 3
// baseline (speedup 1.0000x reference)
#include <cuda_runtime.h>
#include <math.h>
#include <stdint.h>

#define Bm   32
#define Tm   2048
#define Fm   64
#define Hm   256
#define G3   768
#define OUTm 64

// GRU cluster geometry
#define CS    8          // CTAs per cluster
#define NB    2          // batches per cluster
#define NCLUS (Bm / NB)  // 16 clusters
#define JPC   32         // hidden units per CTA
#define NCOL  (3 * JPC)  // 96 recurrent columns per CTA
#define KP    260        // padded weight row stride (260 % 32 == 4 -> conflict-free LDS.128)
#define GRUTHREADS 384

// ---------------- scratch (device globals; no allocation allowed) ----------
__device__ float d_xnT[Tm * Fm * Bm];         // [t][f][b]
__device__ float d_xb1[(size_t)Tm * G3 * Bm]; // [t][c][b]
__device__ float d_h1 [(size_t)Tm * Hm * Bm]; // [t][k][b]
__device__ float d_xb2[(size_t)Tm * G3 * Bm]; // [t][c][b]
__device__ float d_hA[Hm * Bm];               // final h2 [k][b]

__device__ __forceinline__ uint32_t smem_u32(const void* p) {
    uint32_t a;
    asm("{ .reg .u64 t; cvta.to.shared.u64 t, %1; cvt.u32.u64 %0, t; }" : "=r"(a) : "l"(p));
    return a;
}

// ---------------- LayerNorm:  x[B][T][F] -> xnT[t][f][b] --------------------
__global__ void ln_kernel(const float* __restrict__ x,
                          const float* __restrict__ gamma,
                          const float* __restrict__ beta) {
    int t = blockIdx.x;
    int wid = threadIdx.x >> 5, lane = threadIdx.x & 31;
    for (int bb = 0; bb < 4; bb++) {
        int b = wid * 4 + bb;
        float2 v = reinterpret_cast<const float2*>(x + ((size_t)b * Tm + t) * Fm)[lane];
        float s = v.x + v.y;
        float q = v.x * v.x + v.y * v.y;
        #pragma unroll
        for (int o = 16; o; o >>= 1) {
            s += __shfl_down_sync(0xffffffffu, s, o);
            q += __shfl_down_sync(0xffffffffu, q, o);
        }
        s = __shfl_sync(0xffffffffu, s, 0);
        q = __shfl_sync(0xffffffffu, q, 0);
        float mean = s * (1.f / 64.f);
        float var  = q * (1.f / 64.f) - mean * mean;
        float rstd = rsqrtf(var + 1e-3f);
        int f0 = 2 * lane;
        d_xnT[t * (Fm * Bm) + (f0    ) * Bm + b] = (v.x - mean) * rstd * gamma[f0]     + beta[f0];
        d_xnT[t * (Fm * Bm) + (f0 + 1) * Bm + b] = (v.y - mean) * rstd * gamma[f0 + 1] + beta[f0 + 1];
    }
}

// ---------------- GEMM1: xb1[t][c][b] = xnT[t] @ k1 + b1[0] ----------------
#define SM1_FLOATS (Fm * G3 + Fm * Bm)
__global__ void gemm1_kernel(const float* __restrict__ k1,
                             const float* __restrict__ b1) {
    extern __shared__ float sm1[];
    float* ks = sm1;               // [f][c]
    float* As = sm1 + Fm * G3;     // [f][b]
    int t = blockIdx.x, tid = threadIdx.x;
    {
        const float4* src = reinterpret_cast<const float4*>(k1);
        float4* dst = reinterpret_cast<float4*>(ks);
        for (int i = tid; i < (Fm * G3) / 4; i += 256) dst[i] = src[i];
        const float4* a = reinterpret_cast<const float4*>(d_xnT + (size_t)t * Fm * Bm);
        float4* ad = reinterpret_cast<float4*>(As);
        for (int i = tid; i < (Fm * Bm) / 4; i += 256) ad[i] = a[i];
    }
    __syncthreads();
    int wid = tid >> 5, lane = tid & 31;
    for (int ch = 0; ch < 12; ch++) {
        int c0 = wid * 96 + ch * 8;
        float acc[8] = {0, 0, 0, 0, 0, 0, 0, 0};
        #pragma unroll 4
        for (int f = 0; f < Fm; f++) {
            float a = As[f * Bm + lane];
            float4 w0 = *reinterpret_cast<const float4*>(&ks[f * G3 + c0]);
            float4 w1 = *reinterpret_cast<const float4*>(&ks[f * G3 + c0 + 4]);
            acc[0] = fmaf(a, w0.x, acc[0]); acc[1] = fmaf(a, w0.y, acc[1]);
            acc[2] = fmaf(a, w0.z, acc[2]); acc[3] = fmaf(a, w0.w, acc[3]);
            acc[4] = fmaf(a, w1.x, acc[4]); acc[5] = fmaf(a, w1.y, acc[5]);
            acc[6] = fmaf(a, w1.z, acc[6]); acc[7] = fmaf(a, w1.w, acc[7]);
        }
        float* outp = d_xb1 + (size_t)t * G3 * Bm + (size_t)c0 * Bm + lane;
        #pragma unroll
        for (int i = 0; i < 8; i++) outp[i * Bm] = acc[i] + __ldg(&b1[c0 + i]);
    }
}

// ---------------- GEMM2: xb2[t][c][b] = h1[t] @ k2 + b2[0] -----------------
#define SM2_FLOATS (2 * Hm * Bm + Hm * 128)
__global__ void gemm2_kernel(const float* __restrict__ k2,
                             const float* __restrict__ b2) {
    extern __shared__ float sm2[];
    float* As = sm2;                 // 2 * [k][b]
    float* ws = sm2 + 2 * Hm * Bm;   // [k][128]
    int tid = threadIdx.x, wid = tid >> 5, lane = tid & 31;
    int t0 = blockIdx.x * 2;
    {
        const float4* a = reinterpret_cast<const float4*>(d_h1 + (size_t)t0 * Hm * Bm);
        float4* ad = reinterpret_cast<float4*>(As);
        for (int i = tid; i < (2 * Hm * Bm) / 4; i += 256) ad[i] = a[i];
    }
    for (int ct = 0; ct < 6; ct++) {
        __syncthreads();
        for (int i = tid; i < Hm * 32; i += 256) {
            int k = i >> 5, c4 = i & 31;
            *reinterpret_cast<float4*>(&ws[k * 128 + c4 * 4]) =
                *reinterpret_cast<const float4*>(&k2[k * G3 + ct * 128 + c4 * 4]);
        }
        __syncthreads();
        int cw = wid * 16;
        float acc0[16], acc1[16];
        #pragma unroll
        for (int i = 0; i < 16; i++) { acc0[i] = 0.f; acc1[i] = 0.f; }
        #pragma unroll 2
        for (int k = 0; k < Hm; k++) {
            float a0 = As[k * Bm + lane];
            float a1 = As[Hm * Bm + k * Bm + lane];
            float w[16];
            const float* wrow = &ws[k * 128 + cw];
            *reinterpret_cast<float4*>(&w[0])  = *reinterpret_cast<const float4*>(wrow);
            *reinterpret_cast<float4*>(&w[4])  = *reinterpret_cast<const float4*>(wrow + 4);
            *reinterpret_cast<float4*>(&w[8])  = *reinterpret_cast<const float4*>(wrow + 8);
            *reinterpret_cast<float4*>(&w[12]) = *reinterpret_cast<const float4*>(wrow + 12);
            #pragma unroll
            for (int i = 0; i < 16; i++) {
                acc0[i] = fmaf(a0, w[i], acc0[i]);
                acc1[i] = fmaf(a1, w[i], acc1[i]);
            }
        }
        #pragma unroll
        for (int i = 0; i < 16; i++) {
            int c = ct * 128 + cw + i;
            float bias = __ldg(&b2[c]);
            d_xb2[(size_t)(t0    ) * G3 * Bm + (size_t)c * Bm + lane] = acc0[i] + bias;
            d_xb2[(size_t)(t0 + 1) * G3 * Bm + (size_t)c * Bm + lane] = acc1[i] + bias;
        }
    }
}

// ---------------- cluster GRU: batch-partitioned, DSMEM h exchange ----------
// smem layout (floats): ws[NCOL*KP] | hbuf[2][NB][Hm] | sp[4][NCOL][NB]
#define GRU_WS_F   (NCOL * KP)
#define GRU_HB_F   (2 * NB * Hm)
#define GRU_SP_F   (4 * NCOL * NB)
#define GRU_SMEM_F (GRU_WS_F + GRU_HB_F + GRU_SP_F)

__global__ void __launch_bounds__(GRUTHREADS, 1) __cluster_dims__(CS, 1, 1)
gru_cluster_kernel(int which,
                   const float* __restrict__ rk,     // [256][768]
                   const float* __restrict__ bias2)  // recurrent bias row [768]
{
    extern __shared__ float sm[];
    float* ws   = sm;                       // [colid][KP]
    float* hbuf = sm + GRU_WS_F;            // [phase][b][k]
    float* sp   = sm + GRU_WS_F + GRU_HB_F; // [kq][colid][b]

    const float* xb = which ? d_xb2 : d_xb1;

    int tid = threadIdx.x;
    uint32_t rank;
    asm("mov.u32 %0, %%cluster_ctarank;" : "=r"(rank));
    int cbase = (blockIdx.x / CS) * NB;     // first global batch of this cluster

    // ---- load recurrent weights for our 96 columns (once) ----
    for (int idx = tid; idx < NCOL * Hm; idx += GRUTHREADS) {
        int colid = idx % NCOL;             // consecutive tids -> consecutive cols (coalesced LDG)
        int k     = idx / NCOL;
        int g = colid >> 5, jl = colid & 31;
        int col = g * Hm + rank * JPC + jl;
        ws[colid * KP + k] = rk[k * G3 + col];
    }
    // zero both h phase buffers (own smem only)
    for (int idx = tid; idx < GRU_HB_F; idx += GRUTHREADS) hbuf[idx] = 0.f;
    __syncthreads();
    // cluster-wide: everyone's buffers initialized before any DSMEM traffic
    asm volatile("barrier.cluster.arrive.aligned;" ::: "memory");
    asm volatile("barrier.cluster.wait.aligned;" ::: "memory");

    // ---- roles ----
    int colid = tid % NCOL;                 // 0..95
    int kq    = tid / NCOL;                 // 0..3 (tid<384)
    const float* wrow = ws + colid * KP + kq * 64;

    // finalizer role: tid < 64 -> (jl, b)
    int fjl = tid & 31, fb = tid >> 5;
    int fj  = rank * JPC + fjl;             // global hidden index
    int fbg = cbase + fb;                   // global batch
    float bz = bias2[fj], br = bias2[Hm + fj], bh = bias2[2 * Hm + fj];

    // precompute remote hbuf base addresses for all 8 cluster ranks
    uint32_t hb_local = smem_u32(hbuf);
    uint32_t rbase[CS];
    #pragma unroll
    for (int r = 0; r < CS; r++) {
        asm("mapa.shared::cluster.u32 %0, %1, %2;" : "=r"(rbase[r]) : "r"(hb_local), "r"(r));
    }

    for (int t = 0; t < Tm; t++) {
        int rph = t & 1, wph = rph ^ 1;

        // prefetch x-projections (finalizers only; consumed ~1000 cycles later)
        float xz = 0.f, xr = 0.f, xh = 0.f;
        if (tid < NB * JPC) {
            const float* xp = xb + (size_t)t * (G3 * Bm);
            xz = __ldcg(&xp[(fj         ) * Bm + fbg]);
            xr = __ldcg(&xp[(Hm + fj    ) * Bm + fbg]);
            xh = __ldcg(&xp[(2 * Hm + fj) * Bm + fbg]);
        }

        // ---- 96x256x2 dot products, k split 4-ways across thread groups ----
        const float* h0 = hbuf + (rph * NB + 0) * Hm + kq * 64;
        const float* h1 = hbuf + (rph * NB + 1) * Hm + kq * 64;
        float a0 = 0.f, a1 = 0.f, a2 = 0.f, a3 = 0.f;
        #pragma unroll
        for (int k = 0; k < 64; k += 4) {
            float4 w = *reinterpret_cast<const float4*>(wrow + k);
            float4 u = *reinterpret_cast<const float4*>(h0 + k);   // broadcast
            float4 v = *reinterpret_cast<const float4*>(h1 + k);   // broadcast
            a0 = fmaf(w.x, u.x, a0); a1 = fmaf(w.y, u.y, a1);
            a0 = fmaf(w.z, u.z, a0); a1 = fmaf(w.w, u.w, a1);
            a2 = fmaf(w.x, v.x, a2); a3 = fmaf(w.y, v.y, a3);
            a2 = fmaf(w.z, v.z, a2); a3 = fmaf(w.w, v.w, a3);
        }
        sp[(kq * NCOL + colid) * NB + 0] = a0 + a1;
        sp[(kq * NCOL + colid) * NB + 1] = a2 + a3;
        __syncthreads();

        // ---- finalize: gate math + broadcast h_new to all cluster CTAs ----
        if (tid < NB * JPC) {
            float az = bz, ar = br, ah = bh;
            #pragma unroll
            for (int q = 0; q < 4; q++) {
                az += sp[(q * NCOL +          fjl) * NB + fb];
                ar += sp[(q * NCOL + JPC    + fjl) * NB + fb];
                ah += sp[(q * NCOL + 2*JPC  + fjl) * NB + fb];
            }
            float hold = hbuf[(rph * NB + fb) * Hm + fj];
            float z  = 1.f / (1.f + __expf(-(xz + az)));
            float r  = 1.f / (1.f + __expf(-(xr + ar)));
            float hh = tanhf(xh + r * ah);
            float hn = z * hold + (1.f - z) * hh;

            uint32_t off = ((uint32_t)(wph * NB + fb) * Hm + (uint32_t)fj) * 4u;
            #pragma unroll
            for (int rr = 0; rr < CS; rr++) {
                asm volatile("st.shared::cluster.f32 [%0], %1;"
                             :: "r"(rbase[rr] + off), "f"(hn));
            }
            if (which == 0) {
                d_h1[(size_t)t * (Hm * Bm) + fj * Bm + fbg] = hn;
            } else if (t == Tm - 1) {
                d_hA[fj * Bm + fbg] = hn;
            }
        }
        // cluster barrier: release our DSMEM stores / acquire peers'
        asm volatile("barrier.cluster.arrive.aligned;" ::: "memory");
        asm volatile("barrier.cluster.wait.aligned;" ::: "memory");
    }
}

// ---------------- Dense: out[b][o] = h2 @ wd + bd --------------------------
__global__ void dense_kernel(const float* __restrict__ wd,
                             const float* __restrict__ bd,
                             float* __restrict__ out) {
    int gid = blockIdx.x * blockDim.x + threadIdx.x;
    int b = gid >> 6, o = gid & 63;
    float acc = bd[o];
    #pragma unroll 8
    for (int k = 0; k < Hm; k++)
        acc = fmaf(d_hA[k * Bm + b], __ldg(&wd[k * OUTm + o]), acc);
    out[b * OUTm + o] = acc;
}

// ---------------- launch ----------------------------------------------------
extern "C" void kernel_launch(void* const* d_in, const int* in_sizes, int n_in,
                              void* d_out, int out_size) {
    const float* x     = (const float*)d_in[0];
    const float* gamma = (const float*)d_in[1];
    const float* beta  = (const float*)d_in[2];
    const float* k1    = (const float*)d_in[3];
    const float* rk1   = (const float*)d_in[4];
    const float* b1    = (const float*)d_in[5];
    const float* k2    = (const float*)d_in[6];
    const float* rk2   = (const float*)d_in[7];
    const float* b2    = (const float*)d_in[8];
    const float* wd    = (const float*)d_in[9];
    const float* bd    = (const float*)d_in[10];
    float* out = (float*)d_out;

    cudaFuncSetAttribute(gemm1_kernel, cudaFuncAttributeMaxDynamicSharedMemorySize,
                         SM1_FLOATS * sizeof(float));
    cudaFuncSetAttribute(gemm2_kernel, cudaFuncAttributeMaxDynamicSharedMemorySize,
                         SM2_FLOATS * sizeof(float));
    cudaFuncSetAttribute(gru_cluster_kernel, cudaFuncAttributeMaxDynamicSharedMemorySize,
                         GRU_SMEM_F * sizeof(float));

    ln_kernel<<<Tm, 256>>>(x, gamma, beta);
    gemm1_kernel<<<Tm, 256, SM1_FLOATS * sizeof(float)>>>(k1, b1);
    gru_cluster_kernel<<<NCLUS * CS, GRUTHREADS, GRU_SMEM_F * sizeof(float)>>>(0, rk1, b1 + G3);
    gemm2_kernel<<<Tm / 2, 256, SM2_FLOATS * sizeof(float)>>>(k2, b2);
    gru_cluster_kernel<<<NCLUS * CS, GRUTHREADS, GRU_SMEM_F * sizeof(float)>>>(1, rk2, b2 + G3);
    dense_kernel<<<(Bm * OUTm) / 256, 256>>>(wd, bd, out);
}

// round 5
// speedup vs baseline: 1.4303x; 1.4303x over previous
#include <cuda_runtime.h>
#include <math.h>
#include <stdint.h>

#define Bm   32
#define Tm   2048
#define Fm   64
#define Hm   256
#define G3   768
#define OUTm 64
#define NCTA_GRU 128    // 6 recurrent columns (2 hidden units) per CTA

// ---------------- scratch (device globals; no allocation allowed) ----------
__device__ float d_xnT[Tm * Fm * Bm];         // [t][f][b]
__device__ float d_xb1[(size_t)Tm * G3 * Bm]; // [t][c][b]
__device__ float d_h1 [(size_t)Tm * Hm * Bm]; // [t][k][b]
__device__ float d_xb2[(size_t)Tm * G3 * Bm]; // [t][c][b]
// interleaved h ping-pong: index ((k>>1)*32 + b)*2 + (k&1)
__device__ float d_hA[Hm * Bm];
__device__ float d_hB[Hm * Bm];
__device__ unsigned d_bar;

// ---------------- LayerNorm:  x[B][T][F] -> xnT[t][f][b] --------------------
__global__ void ln_kernel(const float* __restrict__ x,
                          const float* __restrict__ gamma,
                          const float* __restrict__ beta) {
    int t = blockIdx.x;
    int wid = threadIdx.x >> 5, lane = threadIdx.x & 31;
    for (int bb = 0; bb < 4; bb++) {
        int b = wid * 4 + bb;
        float2 v = reinterpret_cast<const float2*>(x + ((size_t)b * Tm + t) * Fm)[lane];
        float s = v.x + v.y;
        float q = v.x * v.x + v.y * v.y;
        #pragma unroll
        for (int o = 16; o; o >>= 1) {
            s += __shfl_down_sync(0xffffffffu, s, o);
            q += __shfl_down_sync(0xffffffffu, q, o);
        }
        s = __shfl_sync(0xffffffffu, s, 0);
        q = __shfl_sync(0xffffffffu, q, 0);
        float mean = s * (1.f / 64.f);
        float var  = q * (1.f / 64.f) - mean * mean;
        float rstd = rsqrtf(var + 1e-3f);
        int f0 = 2 * lane;
        d_xnT[t * (Fm * Bm) + (f0    ) * Bm + b] = (v.x - mean) * rstd * gamma[f0]     + beta[f0];
        d_xnT[t * (Fm * Bm) + (f0 + 1) * Bm + b] = (v.y - mean) * rstd * gamma[f0 + 1] + beta[f0 + 1];
    }
}

// ---------------- GEMM1: xb1[t][c][b] = xnT[t] @ k1 + b1[0] ----------------
#define SM1_FLOATS (Fm * G3 + Fm * Bm)
__global__ void gemm1_kernel(const float* __restrict__ k1,
                             const float* __restrict__ b1) {
    extern __shared__ float sm1[];
    float* ks = sm1;               // [f][c]
    float* As = sm1 + Fm * G3;     // [f][b]
    int t = blockIdx.x, tid = threadIdx.x;
    {
        const float4* src = reinterpret_cast<const float4*>(k1);
        float4* dst = reinterpret_cast<float4*>(ks);
        for (int i = tid; i < (Fm * G3) / 4; i += 256) dst[i] = src[i];
        const float4* a = reinterpret_cast<const float4*>(d_xnT + (size_t)t * Fm * Bm);
        float4* ad = reinterpret_cast<float4*>(As);
        for (int i = tid; i < (Fm * Bm) / 4; i += 256) ad[i] = a[i];
    }
    __syncthreads();
    int wid = tid >> 5, lane = tid & 31;
    for (int ch = 0; ch < 12; ch++) {
        int c0 = wid * 96 + ch * 8;
        float acc[8] = {0, 0, 0, 0, 0, 0, 0, 0};
        #pragma unroll 4
        for (int f = 0; f < Fm; f++) {
            float a = As[f * Bm + lane];
            float4 w0 = *reinterpret_cast<const float4*>(&ks[f * G3 + c0]);
            float4 w1 = *reinterpret_cast<const float4*>(&ks[f * G3 + c0 + 4]);
            acc[0] = fmaf(a, w0.x, acc[0]); acc[1] = fmaf(a, w0.y, acc[1]);
            acc[2] = fmaf(a, w0.z, acc[2]); acc[3] = fmaf(a, w0.w, acc[3]);
            acc[4] = fmaf(a, w1.x, acc[4]); acc[5] = fmaf(a, w1.y, acc[5]);
            acc[6] = fmaf(a, w1.z, acc[6]); acc[7] = fmaf(a, w1.w, acc[7]);
        }
        float* outp = d_xb1 + (size_t)t * G3 * Bm + (size_t)c0 * Bm + lane;
        #pragma unroll
        for (int i = 0; i < 8; i++) outp[i * Bm] = acc[i] + __ldg(&b1[c0 + i]);
    }
}

// ---------------- GEMM2: xb2[t][c][b] = h1[t] @ k2 + b2[0] -----------------
#define SM2_FLOATS (2 * Hm * Bm + Hm * 128)
__global__ void gemm2_kernel(const float* __restrict__ k2,
                             const float* __restrict__ b2) {
    extern __shared__ float sm2[];
    float* As = sm2;                 // 2 * [k][b]
    float* ws = sm2 + 2 * Hm * Bm;   // [k][128]
    int tid = threadIdx.x, wid = tid >> 5, lane = tid & 31;
    int t0 = blockIdx.x * 2;
    {
        const float4* a = reinterpret_cast<const float4*>(d_h1 + (size_t)t0 * Hm * Bm);
        float4* ad = reinterpret_cast<float4*>(As);
        for (int i = tid; i < (2 * Hm * Bm) / 4; i += 256) ad[i] = a[i];
    }
    for (int ct = 0; ct < 6; ct++) {
        __syncthreads();
        for (int i = tid; i < Hm * 32; i += 256) {
            int k = i >> 5, c4 = i & 31;
            *reinterpret_cast<float4*>(&ws[k * 128 + c4 * 4]) =
                *reinterpret_cast<const float4*>(&k2[k * G3 + ct * 128 + c4 * 4]);
        }
        __syncthreads();
        int cw = wid * 16;
        float acc0[16], acc1[16];
        #pragma unroll
        for (int i = 0; i < 16; i++) { acc0[i] = 0.f; acc1[i] = 0.f; }
        #pragma unroll 2
        for (int k = 0; k < Hm; k++) {
            float a0 = As[k * Bm + lane];
            float a1 = As[Hm * Bm + k * Bm + lane];
            float w[16];
            const float* wrow = &ws[k * 128 + cw];
            *reinterpret_cast<float4*>(&w[0])  = *reinterpret_cast<const float4*>(wrow);
            *reinterpret_cast<float4*>(&w[4])  = *reinterpret_cast<const float4*>(wrow + 4);
            *reinterpret_cast<float4*>(&w[8])  = *reinterpret_cast<const float4*>(wrow + 8);
            *reinterpret_cast<float4*>(&w[12]) = *reinterpret_cast<const float4*>(wrow + 12);
            #pragma unroll
            for (int i = 0; i < 16; i++) {
                acc0[i] = fmaf(a0, w[i], acc0[i]);
                acc1[i] = fmaf(a1, w[i], acc1[i]);
            }
        }
        #pragma unroll
        for (int i = 0; i < 16; i++) {
            int c = ct * 128 + cw + i;
            float bias = __ldg(&b2[c]);
            d_xb2[(size_t)(t0    ) * G3 * Bm + (size_t)c * Bm + lane] = acc0[i] + bias;
            d_xb2[(size_t)(t0 + 1) * G3 * Bm + (size_t)c * Bm + lane] = acc1[i] + bias;
        }
    }
}

// ---------------- persistent GRU: 128 CTAs, FFMA2, release/acquire barrier --
__global__ void __launch_bounds__(256, 1)
gru_kernel(int which,
           const float* __restrict__ rk,     // [256][768]
           const float* __restrict__ bias2)  // recurrent bias row [768]
{
    const float* xb = which ? d_xb2 : d_xb1;

    __shared__ __align__(16) float hs[Hm * Bm];   // interleaved [k2][b][2], 32KB
    __shared__ __align__(16) float ws[6 * Hm];    // [jl*3+g][k], 6KB
    __shared__ float ps[2 * 3 * 4 * Bm];          // [jl][g][kq][b], 3KB

    int tid  = threadIdx.x;
    int wid  = tid >> 5, lane = tid & 31;
    int jl   = wid & 1;           // unit within CTA
    int kq   = wid >> 1;          // k quarter
    int j    = blockIdx.x * 2 + jl;  // (for warps; finalize recomputes)

    // ---- one-time: load 6 weight columns (2 units x 3 gates) ----
    for (int idx = tid; idx < 6 * Hm; idx += 256) {
        int k = idx & 255, jg = idx >> 8;       // jg = jl*3+g
        int jj = blockIdx.x * 2 + (jg >= 3);    // unit
        int g  = jg % 3;
        ws[idx] = rk[k * G3 + g * Hm + jj];
    }

    // finalize-role constants (tid < 64)
    int fj = blockIdx.x * 2 + (tid >> 5);
    float bz = bias2[fj], br = bias2[Hm + fj], bh = bias2[2 * Hm + fj];

    __syncthreads();

    const float* wz = ws + (jl * 3 + 0) * Hm + kq * 64;
    const float* wr = ws + (jl * 3 + 1) * Hm + kq * 64;
    const float* wh = ws + (jl * 3 + 2) * Hm + kq * 64;
    const float* hbase = hs + kq * 2048 + lane * 2;

    unsigned tgt = NCTA_GRU;
    unsigned* barp = &d_bar;

    for (int t = 0; t < Tm; t++) {
        const float* hr = (t & 1) ? d_hB : d_hA;
        float*       hw = (t & 1) ? d_hA : d_hB;

        // prefetch x-projections (finalize threads; consumed after compute)
        float xz = 0.f, xr = 0.f, xh = 0.f;
        if (tid < 64) {
            const float* xp = xb + (size_t)t * (G3 * Bm);
            xz = __ldcg(&xp[(fj         ) * Bm + lane]);
            xr = __ldcg(&xp[(Hm + fj    ) * Bm + lane]);
            xh = __ldcg(&xp[(2 * Hm + fj) * Bm + lane]);
        }

        // stage h (raw copy, layout identical)
        {
            const float4* src = reinterpret_cast<const float4*>(hr);
            float4* dst = reinterpret_cast<float4*>(hs);
            #pragma unroll
            for (int i = 0; i < 8; i++) dst[tid + i * 256] = __ldcg(&src[tid + i * 256]);
        }
        __syncthreads();

        // ---- partial dots: 3 gates x 64 k per warp, f32x2 packed ----
        uint64_t az0 = 0, az1 = 0, ar0 = 0, ar1 = 0, ah0 = 0, ah1 = 0;
        #pragma unroll
        for (int i = 0; i < 32; i += 2) {
            uint64_t h0 = *reinterpret_cast<const uint64_t*>(hbase + i * 64);
            uint64_t h1 = *reinterpret_cast<const uint64_t*>(hbase + i * 64 + 64);
            float4 zf = *reinterpret_cast<const float4*>(wz + 2 * i);
            float4 rf = *reinterpret_cast<const float4*>(wr + 2 * i);
            float4 hf = *reinterpret_cast<const float4*>(wh + 2 * i);
            uint64_t z0, z1, r0, r1, q0, q1;
            asm("mov.b64 %0, {%1,%2};" : "=l"(z0) : "f"(zf.x), "f"(zf.y));
            asm("mov.b64 %0, {%1,%2};" : "=l"(z1) : "f"(zf.z), "f"(zf.w));
            asm("mov.b64 %0, {%1,%2};" : "=l"(r0) : "f"(rf.x), "f"(rf.y));
            asm("mov.b64 %0, {%1,%2};" : "=l"(r1) : "f"(rf.z), "f"(rf.w));
            asm("mov.b64 %0, {%1,%2};" : "=l"(q0) : "f"(hf.x), "f"(hf.y));
            asm("mov.b64 %0, {%1,%2};" : "=l"(q1) : "f"(hf.z), "f"(hf.w));
            asm("fma.rn.f32x2 %0, %1, %2, %0;" : "+l"(az0) : "l"(z0), "l"(h0));
            asm("fma.rn.f32x2 %0, %1, %2, %0;" : "+l"(ar0) : "l"(r0), "l"(h0));
            asm("fma.rn.f32x2 %0, %1, %2, %0;" : "+l"(ah0) : "l"(q0), "l"(h0));
            asm("fma.rn.f32x2 %0, %1, %2, %0;" : "+l"(az1) : "l"(z1), "l"(h1));
            asm("fma.rn.f32x2 %0, %1, %2, %0;" : "+l"(ar1) : "l"(r1), "l"(h1));
            asm("fma.rn.f32x2 %0, %1, %2, %0;" : "+l"(ah1) : "l"(q1), "l"(h1));
        }
        float lo, hi, sz, sr, sh;
        asm("mov.b64 {%0,%1}, %2;" : "=f"(lo), "=f"(hi) : "l"(az0)); sz = lo + hi;
        asm("mov.b64 {%0,%1}, %2;" : "=f"(lo), "=f"(hi) : "l"(az1)); sz += lo + hi;
        asm("mov.b64 {%0,%1}, %2;" : "=f"(lo), "=f"(hi) : "l"(ar0)); sr = lo + hi;
        asm("mov.b64 {%0,%1}, %2;" : "=f"(lo), "=f"(hi) : "l"(ar1)); sr += lo + hi;
        asm("mov.b64 {%0,%1}, %2;" : "=f"(lo), "=f"(hi) : "l"(ah0)); sh = lo + hi;
        asm("mov.b64 {%0,%1}, %2;" : "=f"(lo), "=f"(hi) : "l"(ah1)); sh += lo + hi;
        ps[((jl * 3 + 0) * 4 + kq) * Bm + lane] = sz;
        ps[((jl * 3 + 1) * 4 + kq) * Bm + lane] = sr;
        ps[((jl * 3 + 2) * 4 + kq) * Bm + lane] = sh;
        __syncthreads();

        // ---- finalize (64 threads: 2 units x 32 batches) ----
        if (tid < 64) {
            int fjl = tid >> 5;
            float az = bz, ar = br, ah = bh;
            #pragma unroll
            for (int q = 0; q < 4; q++) {
                az += ps[((fjl * 3 + 0) * 4 + q) * Bm + lane];
                ar += ps[((fjl * 3 + 1) * 4 + q) * Bm + lane];
                ah += ps[((fjl * 3 + 2) * 4 + q) * Bm + lane];
            }
            float hold = hs[((fj >> 1) * Bm + lane) * 2 + (fj & 1)];
            float z  = 1.f / (1.f + __expf(-(xz + az)));
            float r  = 1.f / (1.f + __expf(-(xr + ar)));
            float hh = tanhf(xh + r * ah);
            float hn = z * hold + (1.f - z) * hh;
            __stcg(&hw[((fj >> 1) * Bm + lane) * 2 + (fj & 1)], hn);
            if (which == 0)
                __stcg(&d_h1[(size_t)t * (Hm * Bm) + fj * Bm + lane], hn);
        }
        __syncthreads();   // all stores done before tid0's release

        if (tid == 0) {
            asm volatile("red.release.gpu.add.u32 [%0], %1;" :: "l"(barp), "r"(1u) : "memory");
            unsigned v;
            do {
                asm volatile("ld.acquire.gpu.u32 %0, [%1];" : "=r"(v) : "l"(barp) : "memory");
            } while (v < tgt);
        }
        tgt += NCTA_GRU;
        __syncthreads();
    }
}

// ---------------- Dense: out[b][o] = h2 @ wd + bd (h2 interleaved in d_hA) --
__global__ void dense_kernel(const float* __restrict__ wd,
                             const float* __restrict__ bd,
                             float* __restrict__ out) {
    int gid = blockIdx.x * blockDim.x + threadIdx.x;
    int b = gid >> 6, o = gid & 63;
    float acc = bd[o];
    #pragma unroll 8
    for (int k = 0; k < Hm; k++)
        acc = fmaf(d_hA[((k >> 1) * Bm + b) * 2 + (k & 1)], __ldg(&wd[k * OUTm + o]), acc);
    out[b * OUTm + o] = acc;
}

// ---------------- launch ----------------------------------------------------
extern "C" void kernel_launch(void* const* d_in, const int* in_sizes, int n_in,
                              void* d_out, int out_size) {
    const float* x     = (const float*)d_in[0];
    const float* gamma = (const float*)d_in[1];
    const float* beta  = (const float*)d_in[2];
    const float* k1    = (const float*)d_in[3];
    const float* rk1   = (const float*)d_in[4];
    const float* b1    = (const float*)d_in[5];
    const float* k2    = (const float*)d_in[6];
    const float* rk2   = (const float*)d_in[7];
    const float* b2    = (const float*)d_in[8];
    const float* wd    = (const float*)d_in[9];
    const float* bd    = (const float*)d_in[10];
    float* out = (float*)d_out;

    cudaFuncSetAttribute(gemm1_kernel, cudaFuncAttributeMaxDynamicSharedMemorySize,
                         SM1_FLOATS * sizeof(float));
    cudaFuncSetAttribute(gemm2_kernel, cudaFuncAttributeMaxDynamicSharedMemorySize,
                         SM2_FLOATS * sizeof(float));
    void *barp = nullptr, *hap = nullptr;
    cudaGetSymbolAddress(&barp, d_bar);
    cudaGetSymbolAddress(&hap, d_hA);

    ln_kernel<<<Tm, 256>>>(x, gamma, beta);
    gemm1_kernel<<<Tm, 256, SM1_FLOATS * sizeof(float)>>>(k1, b1);
    cudaMemsetAsync(barp, 0, sizeof(unsigned));
    cudaMemsetAsync(hap, 0, Hm * Bm * sizeof(float));
    gru_kernel<<<NCTA_GRU, 256>>>(0, rk1, b1 + G3);   // writes d_h1
    gemm2_kernel<<<Tm / 2, 256, SM2_FLOATS * sizeof(float)>>>(k2, b2);
    cudaMemsetAsync(barp, 0, sizeof(unsigned));
    cudaMemsetAsync(hap, 0, Hm * Bm * sizeof(float));
    gru_kernel<<<NCTA_GRU, 256>>>(1, rk2, b2 + G3);   // final state -> d_hA (t=2047 writes A)
    dense_kernel<<<(Bm * OUTm) / 256, 256>>>(wd, bd, out);
}